// round 6
// baseline (speedup 1.0000x reference)
#include <cuda_runtime.h>
#include <cstdint>

#define D     512
#define NWAY  64
#define MT    128
#define NCH   8          // K chunks of 64
#define NTH   256

#define QS    (127.0f / 6.0f)      // 1/s
#define SDV   (6.0f / 127.0f)      // s

// ---- dynamic smem layout ----
#define A_BUF  16384               // 128 rows x 128B (h bytes 0-63 | l bytes 64-127)
#define B_BUF  8192                // limbs {h,l} x 32 kpair-rows x 128B
#define SM_XN2  0                  // 128 floats
#define SM_SPN  512
#define SM_SIPN 768
#define SM_A    1024               // 2 buffers
#define SM_B    (SM_A + 2 * A_BUF) // 33792
#define SMEM_TOTAL (SM_B + 2 * B_BUF)   // 50176 -> 2 CTAs/SM easily

// Pre-quantized prototypes: [chunk][limb][kpair(32)][n(64)] uint16 (2 packed s8)
__device__ unsigned short g_bq[NCH * 2 * 32 * NWAY];
__device__ float g_pn[NWAY];
__device__ float g_ipn[NWAY];

// ---------------- PTX helpers (baseline sm_80+) ----------------
__device__ __forceinline__ uint32_t smem_u32(const void* p) {
    uint32_t a;
    asm("{ .reg .u64 t; cvta.to.shared.u64 t, %1; cvt.u32.u64 %0, t; }" : "=r"(a) : "l"(p));
    return a;
}
__device__ __forceinline__ void ldsm4(uint32_t* r, uint32_t addr) {
    asm volatile("ldmatrix.sync.aligned.m8n8.x4.shared.b16 {%0,%1,%2,%3}, [%4];"
                 : "=r"(r[0]), "=r"(r[1]), "=r"(r[2]), "=r"(r[3]) : "r"(addr));
}
__device__ __forceinline__ void ldsm4t(uint32_t* r, uint32_t addr) {
    asm volatile("ldmatrix.sync.aligned.m8n8.x4.trans.shared.b16 {%0,%1,%2,%3}, [%4];"
                 : "=r"(r[0]), "=r"(r[1]), "=r"(r[2]), "=r"(r[3]) : "r"(addr));
}
__device__ __forceinline__ void imma(int* d, const uint32_t* a, const uint32_t* b) {
    asm volatile(
        "mma.sync.aligned.m16n8k32.row.col.s32.s8.s8.s32 "
        "{%0,%1,%2,%3}, {%4,%5,%6,%7}, {%8,%9}, {%0,%1,%2,%3};"
        : "+r"(d[0]), "+r"(d[1]), "+r"(d[2]), "+r"(d[3])
        : "r"(a[0]), "r"(a[1]), "r"(a[2]), "r"(a[3]), "r"(b[0]), "r"(b[1]));
}
__device__ __forceinline__ void cp16(uint32_t saddr, const void* g) {
    asm volatile("cp.async.ca.shared.global [%0], [%1], 16;" :: "r"(saddr), "l"(g));
}
#define CP_COMMIT() asm volatile("cp.async.commit_group;" ::: "memory")
#define CP_WAIT0()  asm volatile("cp.async.wait_group 0;" ::: "memory")

// pack 4 s32 -> 4 saturated s8 bytes, little-endian a0..a3
__device__ __forceinline__ uint32_t pack4(int a0, int a1, int a2, int a3) {
    uint32_t t, r;
    asm("cvt.pack.sat.s8.s32.b32 %0, %1, %2, %3;" : "=r"(t) : "r"(a3), "r"(a2), "r"(0));
    asm("cvt.pack.sat.s8.s32.b32 %0, %1, %2, %3;" : "=r"(r) : "r"(a1), "r"(a0), "r"(t));
    return r;
}
// quantize float4 -> h-word + l-word (2-limb s8)
__device__ __forceinline__ void quant4(float4 v, uint32_t& hw, uint32_t& lw) {
    int h0 = __float2int_rn(v.x * QS), m0 = __float2int_rn(v.x * (256.0f * QS));
    int h1 = __float2int_rn(v.y * QS), m1 = __float2int_rn(v.y * (256.0f * QS));
    int h2 = __float2int_rn(v.z * QS), m2 = __float2int_rn(v.z * (256.0f * QS));
    int h3 = __float2int_rn(v.w * QS), m3 = __float2int_rn(v.w * (256.0f * QS));
    hw = pack4(h0, h1, h2, h3);
    lw = pack4(m0 - (h0 << 8), m1 - (h1 << 8), m2 - (h2 << 8), m3 - (h3 << 8));
}

// One block per prototype: norms + 2-limb s8 quant into [chunk][limb][kpair][n]
__global__ void proto_prep_kernel(const float* __restrict__ p) {
    int c = blockIdx.x, t = threadIdx.x;   // 64 blocks x 128 threads
    float4 v = *(const float4*)(p + c * D + t * 4);
    float s = v.x * v.x + v.y * v.y + v.z * v.z + v.w * v.w;
    uint32_t hw, lw;
    quant4(v, hw, lw);
    int chunk = (t * 4) >> 6;
    int kp    = ((t * 4) >> 1) & 31;    // kpair within chunk (covers kp, kp+1)
    g_bq[((chunk * 2 + 0) * 32 + kp    ) * 64 + c] = (unsigned short)(hw & 0xffff);
    g_bq[((chunk * 2 + 0) * 32 + kp + 1) * 64 + c] = (unsigned short)(hw >> 16);
    g_bq[((chunk * 2 + 1) * 32 + kp    ) * 64 + c] = (unsigned short)(lw & 0xffff);
    g_bq[((chunk * 2 + 1) * 32 + kp + 1) * 64 + c] = (unsigned short)(lw >> 16);

    #pragma unroll
    for (int o = 16; o; o >>= 1) s += __shfl_xor_sync(0xffffffffu, s, o);
    __shared__ float ws[4];
    if ((t & 31) == 0) ws[t >> 5] = s;
    __syncthreads();
    if (t == 0) {
        float n2 = ws[0] + ws[1] + ws[2] + ws[3];
        float pn = sqrtf(n2);
        g_pn[c] = pn; g_ipn[c] = 1.0f / pn;
    }
}

__global__ __launch_bounds__(NTH, 2) void cosine_imma_kernel(
    const float* __restrict__ x, float* __restrict__ out) {

    extern __shared__ char smem[];
    const uint32_t sb = smem_u32(smem);
    const int tid  = threadIdx.x;
    const int wid  = tid >> 5;
    const int lane = tid & 31;
    const int mw   = wid & 3;         // warp m-tile (32 rows)
    const int nw   = wid >> 2;        // warp n-tile (32 cols)
    const long rowBase = (long)blockIdx.x * MT;

    float* xn2s = (float*)(smem + SM_XN2);
    float* spn  = (float*)(smem + SM_SPN);
    float* sipn = (float*)(smem + SM_SIPN);
    if (tid < NWAY) { spn[tid] = g_pn[tid]; sipn[tid] = g_ipn[tid]; }

    // ---- B chunk staging (cp.async, pre-quantized) ----
    auto stage_b = [&](int chunk, int buf) {
        uint32_t base = sb + SM_B + (uint32_t)(buf * B_BUF);
        #pragma unroll
        for (int i = 0; i < 2; i++) {
            int idx  = tid + i * NTH;           // 0..511
            int limb = idx >> 8, kp = (idx >> 3) & 31, n8 = (idx & 7) * 8;
            const unsigned short* src = g_bq + ((chunk * 2 + limb) * 32 + kp) * 64 + n8;
            uint32_t dst = base + (uint32_t)(limb * 4096 + kp * 128 + (((kp & 7) * 16) ^ (n8 * 2)));
            cp16(dst, src);
        }
    };

    // ---- A staging: thread t -> row t>>1, k-half (t&1)*32 of each 64-chunk ----
    const int r  = tid >> 1;
    const int kh = tid & 1;
    const uint32_t arow128 = (uint32_t)(r * 128);
    const uint32_t asw_st  = (uint32_t)((r & 7) * 16);
    const float* xrow = x + (rowBase + r) * D + kh * 32;
    float na = 0.f;

    // quantize one 16-k phase (4 float4) and STS into buffer 'abuf'
    auto stage_a_phase = [&](const float4* v, uint32_t abuf, int ph) {
        uint32_t hw[4], lw[4];
        #pragma unroll
        for (int i = 0; i < 4; i++) {
            na += v[i].x * v[i].x + v[i].y * v[i].y + v[i].z * v[i].z + v[i].w * v[i].w;
            quant4(v[i], hw[i], lw[i]);
        }
        uint32_t kb = (uint32_t)(kh * 32 + ph * 16);
        uint32_t ha = abuf + arow128 + (asw_st ^ kb);
        uint32_t la = abuf + arow128 + (asw_st ^ (64u + kb));
        asm volatile("st.shared.v4.b32 [%0], {%1,%2,%3,%4};" :: "r"(ha),
                     "r"(hw[0]), "r"(hw[1]), "r"(hw[2]), "r"(hw[3]));
        asm volatile("st.shared.v4.b32 [%0], {%1,%2,%3,%4};" :: "r"(la),
                     "r"(lw[0]), "r"(lw[1]), "r"(lw[2]), "r"(lw[3]));
    };

    {   // prologue: chunk 0 (A both phases + B) into buf 0
        stage_b(0, 0);
        CP_COMMIT();
        float4 va[4];
        #pragma unroll
        for (int ph = 0; ph < 2; ph++) {
            const float4* xg = (const float4*)(xrow + ph * 16);
            #pragma unroll
            for (int i = 0; i < 4; i++) va[i] = xg[i];
            stage_a_phase(va, sb + SM_A, ph);
        }
        CP_WAIT0();
    }
    __syncthreads();

    // ---- per-lane ldsm address constants ----
    const int j = lane & 7, g = lane >> 3;
    uint32_t aoff[2];
    #pragma unroll
    for (int mt = 0; mt < 2; mt++)
        aoff[mt] = (uint32_t)((mw * 32 + mt * 16 + (g & 1) * 8 + j) * 128);
    const uint32_t asw = (uint32_t)(j * 16);
    const uint32_t akg = (uint32_t)((g >> 1) * 16);
    const uint32_t brow = (uint32_t)(((g & 1) * 8 + j) * 128);
    uint32_t bx[2];
    #pragma unroll
    for (int p = 0; p < 2; p++) {
        int nb = nw * 32 + p * 16 + (g >> 1) * 8;
        bx[p] = (uint32_t)((j * 16) ^ (nb * 2));
    }

    int acc1[2][4][4], acc2[2][4][4];
    #pragma unroll
    for (int mt = 0; mt < 2; mt++)
        #pragma unroll
        for (int q = 0; q < 4; q++)
            #pragma unroll
            for (int e = 0; e < 4; e++) { acc1[mt][q][e] = 0; acc2[mt][q][e] = 0; }

    // one k32 MMA step
    auto mma_step = [&](uint32_t abase, uint32_t bbase, int s) {
        uint32_t ah[2][4], al[2][4], bq[2][4][2];
        #pragma unroll
        for (int mt = 0; mt < 2; mt++) {
            ldsm4(ah[mt], abase + aoff[mt] + (asw ^ (uint32_t)(s * 32 + akg)));
            ldsm4(al[mt], abase + aoff[mt] + (asw ^ (uint32_t)(64 + s * 32 + akg)));
        }
        #pragma unroll
        for (int p = 0; p < 2; p++) {
            uint32_t t4[4];
            ldsm4t(t4, bbase + brow + (uint32_t)(s * 2048) + bx[p]);
            bq[0][2*p][0] = t4[0]; bq[0][2*p][1] = t4[1];
            bq[0][2*p+1][0] = t4[2]; bq[0][2*p+1][1] = t4[3];
            ldsm4t(t4, bbase + 4096u + brow + (uint32_t)(s * 2048) + bx[p]);
            bq[1][2*p][0] = t4[0]; bq[1][2*p][1] = t4[1];
            bq[1][2*p+1][0] = t4[2]; bq[1][2*p+1][1] = t4[3];
        }
        #pragma unroll
        for (int mt = 0; mt < 2; mt++)
            #pragma unroll
            for (int q = 0; q < 4; q++) {
                imma(acc1[mt][q], ah[mt], bq[0][q]);   // h*h'
                imma(acc2[mt][q], ah[mt], bq[1][q]);   // h*l'
                imma(acc2[mt][q], al[mt], bq[0][q]);   // l*h'
            }
    };

    // ---- main loop over K chunks ----
    for (int kt = 0; kt < NCH; kt++) {
        const uint32_t abase = sb + SM_A + (uint32_t)((kt & 1) * A_BUF);
        const uint32_t bbase = sb + SM_B + (uint32_t)((kt & 1) * B_BUF);
        const uint32_t anext = sb + SM_A + (uint32_t)(((kt + 1) & 1) * A_BUF);

        float4 va[4];
        if (kt < NCH - 1) {
            const float4* xg = (const float4*)(xrow + (kt + 1) * 64);
            #pragma unroll
            for (int i = 0; i < 4; i++) va[i] = xg[i];
            stage_b(kt + 1, (kt + 1) & 1);
            CP_COMMIT();
        }

        mma_step(abase, bbase, 0);

        if (kt < NCH - 1) {
            stage_a_phase(va, anext, 0);        // next buffer is free (freed at kt-1 sync)
            const float4* xg = (const float4*)(xrow + (kt + 1) * 64 + 16);
            #pragma unroll
            for (int i = 0; i < 4; i++) va[i] = xg[i];
        }

        mma_step(abase, bbase, 1);

        if (kt < NCH - 1) {
            stage_a_phase(va, anext, 1);
            CP_WAIT0();
        }
        __syncthreads();
    }

    // ---- row norms: pair-reduce (two threads per row) ----
    {
        float s = na + __shfl_xor_sync(0xffffffffu, na, 1);
        if ((tid & 1) == 0) xn2s[r] = s;
    }
    __syncthreads();

    // ---- epilogue: dequant + scale + store ----
    const float SD2  = SDV * SDV;
    const float SD2q = SD2 * (1.0f / 256.0f);
    const int gr = lane >> 2, ci = lane & 3;
    #pragma unroll
    for (int mt = 0; mt < 2; mt++) {
        #pragma unroll
        for (int rr = 0; rr < 2; rr++) {
            int row = mw * 32 + mt * 16 + rr * 8 + gr;
            float n2 = xn2s[row];
            float invxn = rsqrtf(n2);
            float xn = n2 * invxn;
            float* og = out + (rowBase + row) * NWAY;
            #pragma unroll
            for (int q = 0; q < 4; q++) {
                int c0 = nw * 32 + q * 8 + ci * 2;
                float d0 = SD2 * (float)acc1[mt][q][rr * 2]     + SD2q * (float)acc2[mt][q][rr * 2];
                float d1 = SD2 * (float)acc1[mt][q][rr * 2 + 1] + SD2q * (float)acc2[mt][q][rr * 2 + 1];
                float den0 = xn * spn[c0], den1 = xn * spn[c0 + 1];
                float s0 = (den0 < 1e-8f) ? 1e8f : invxn * sipn[c0];
                float s1 = (den1 < 1e-8f) ? 1e8f : invxn * sipn[c0 + 1];
                *(float2*)(og + c0) = make_float2(-d0 * s0, -d1 * s1);
            }
        }
    }
}

extern "C" void kernel_launch(void* const* d_in, const int* in_sizes, int n_in,
                              void* d_out, int out_size) {
    const float* x      = (const float*)d_in[0];
    const float* protos = (const float*)d_in[1];
    float* out          = (float*)d_out;
    int B = in_sizes[0] / D;   // 65536

    cudaFuncSetAttribute(cosine_imma_kernel,
                         cudaFuncAttributeMaxDynamicSharedMemorySize, SMEM_TOTAL);

    proto_prep_kernel<<<NWAY, 128>>>(protos);
    cosine_imma_kernel<<<B / MT, NTH, SMEM_TOTAL>>>(x, out);
}

// round 7
// speedup vs baseline: 1.9922x; 1.9922x over previous
#include <cuda_runtime.h>
#include <cuda_fp16.h>
#include <cstdint>

#define D     512
#define NWAY  64
#define MT    128
#define KT    64
#define NCH   (D / KT)     // 8
#define NTH   256

// ---- dynamic smem layout ----
#define A_BUF  16384                    // 128 rows x 128B (64 fp16 = one k-chunk)
#define B_BUF  8192                     // 64 k-rows x 128B (64 n fp16)
#define SM_XN2  0                       // 128 floats
#define SM_SPN  512                     // 64 floats
#define SM_SIPN 768                     // 64 floats
#define SM_A    1024                    // 2 x A_BUF = 32KB
#define SM_B    (SM_A + 2 * A_BUF)      // 33792: 2 x B_BUF = 16KB
#define SMEM_TOTAL (SM_B + 2 * B_BUF)   // 50176 bytes

// Pre-converted prototypes, fp16 [k][n] layout (for ldmatrix.trans B frags)
__device__ unsigned short g_bh[D * NWAY];
__device__ float g_pn[NWAY];
__device__ float g_ipn[NWAY];

// One block per prototype: norms + fp16 convert into [k][n] global.
__global__ void proto_prep_kernel(const float* __restrict__ p) {
    int c = blockIdx.x, t = threadIdx.x;   // 64 blocks x 128 threads
    float4 v = *(const float4*)(p + c * D + t * 4);
    float s = v.x * v.x + v.y * v.y + v.z * v.z + v.w * v.w;
    __half h0 = __float2half_rn(v.x), h1 = __float2half_rn(v.y);
    __half h2 = __float2half_rn(v.z), h3 = __float2half_rn(v.w);
    g_bh[(t * 4 + 0) * NWAY + c] = __half_as_ushort(h0);
    g_bh[(t * 4 + 1) * NWAY + c] = __half_as_ushort(h1);
    g_bh[(t * 4 + 2) * NWAY + c] = __half_as_ushort(h2);
    g_bh[(t * 4 + 3) * NWAY + c] = __half_as_ushort(h3);

    #pragma unroll
    for (int o = 16; o; o >>= 1) s += __shfl_xor_sync(0xffffffffu, s, o);
    __shared__ float ws[4];
    if ((t & 31) == 0) ws[t >> 5] = s;
    __syncthreads();
    if (t == 0) {
        float n2 = ws[0] + ws[1] + ws[2] + ws[3];
        float pn = sqrtf(n2);
        g_pn[c] = pn; g_ipn[c] = 1.0f / pn;
    }
}

// ---------------- PTX helpers (baseline sm_80+) ----------------
__device__ __forceinline__ uint32_t smem_u32(const void* p) {
    uint32_t a;
    asm("{ .reg .u64 t; cvta.to.shared.u64 t, %1; cvt.u32.u64 %0, t; }" : "=r"(a) : "l"(p));
    return a;
}
__device__ __forceinline__ void ldsm4(uint32_t* r, uint32_t addr) {
    asm volatile("ldmatrix.sync.aligned.m8n8.x4.shared.b16 {%0,%1,%2,%3}, [%4];"
                 : "=r"(r[0]), "=r"(r[1]), "=r"(r[2]), "=r"(r[3]) : "r"(addr));
}
__device__ __forceinline__ void ldsm4t(uint32_t* r, uint32_t addr) {
    asm volatile("ldmatrix.sync.aligned.m8n8.x4.trans.shared.b16 {%0,%1,%2,%3}, [%4];"
                 : "=r"(r[0]), "=r"(r[1]), "=r"(r[2]), "=r"(r[3]) : "r"(addr));
}
__device__ __forceinline__ void mma16816(float* d, const uint32_t* a, const uint32_t* b) {
    asm volatile(
        "mma.sync.aligned.m16n8k16.row.col.f32.f16.f16.f32 "
        "{%0,%1,%2,%3}, {%4,%5,%6,%7}, {%8,%9}, {%0,%1,%2,%3};"
        : "+f"(d[0]), "+f"(d[1]), "+f"(d[2]), "+f"(d[3])
        : "r"(a[0]), "r"(a[1]), "r"(a[2]), "r"(a[3]), "r"(b[0]), "r"(b[1]));
}
__device__ __forceinline__ void cp16(uint32_t saddr, const void* g) {
    asm volatile("cp.async.ca.shared.global [%0], [%1], 16;" :: "r"(saddr), "l"(g));
}
#define CP_COMMIT() asm volatile("cp.async.commit_group;" ::: "memory")
#define CP_WAIT0()  asm volatile("cp.async.wait_group 0;" ::: "memory")

// float4 -> 4 packed fp16 (rn)
__device__ __forceinline__ void cvt4h(float4 v, uint2& h) {
    asm("cvt.rn.f16x2.f32 %0, %1, %2;" : "=r"(h.x) : "f"(v.y), "f"(v.x));
    asm("cvt.rn.f16x2.f32 %0, %1, %2;" : "=r"(h.y) : "f"(v.w), "f"(v.z));
}

__global__ __launch_bounds__(NTH, 2) void cosine_hmma_kernel(
    const float* __restrict__ x, float* __restrict__ out) {

    extern __shared__ char smem[];
    const uint32_t sb = smem_u32(smem);
    const int tid  = threadIdx.x;
    const int wid  = tid >> 5;
    const int lane = tid & 31;
    const int mw   = wid & 3;         // warp m-tile (32 rows)
    const int nw   = wid >> 2;        // warp n-tile (32 cols)
    const long rowBase = (long)blockIdx.x * MT;

    float* xn2s = (float*)(smem + SM_XN2);
    float* spn  = (float*)(smem + SM_SPN);
    float* sipn = (float*)(smem + SM_SIPN);
    if (tid < NWAY) { spn[tid] = g_pn[tid]; sipn[tid] = g_ipn[tid]; }

    // ---- B chunk staging via cp.async (pre-converted fp16 [k][n]) ----
    // smem B tile: 64 k-rows x 128B, SW: off = k*128 + (2n ^ ((k&7)*16))
    auto stage_b = [&](int kt, int buf) {
        const char* bh = (const char*)g_bh + kt * 8192;
        uint32_t base = sb + SM_B + (uint32_t)(buf * B_BUF);
        #pragma unroll
        for (int i = 0; i < 2; i++) {
            int c = tid + i * NTH;            // uint4 index (0..511)
            int k = c >> 3, n0 = (c & 7) * 8;
            uint32_t off = (uint32_t)(k * 128 + ((2 * n0) ^ ((k & 7) * 16)));
            cp16(base + off, bh + c * 16);
        }
    };

    // ---- A staging: thread t -> row t>>1, k-half (t&1)*32 of the 64-chunk ----
    const int arow_t = tid >> 1;
    const int acol0  = (tid & 1) * 32;
    const uint32_t a_rowpart = (uint32_t)(arow_t * 128);
    const uint32_t a_sw      = (uint32_t)((arow_t & 7) * 16);
    float na = 0.f;
    float4 va[8];

    {   // prologue: A chunk 0 + B chunk 0 into buf 0
        const float4* xg = (const float4*)(x + (rowBase + arow_t) * D + acol0);
        #pragma unroll
        for (int i = 0; i < 8; i++) va[i] = xg[i];
        stage_b(0, 0);
        CP_COMMIT();
        #pragma unroll
        for (int i = 0; i < 8; i++) {
            float4 v = va[i];
            na += v.x * v.x + v.y * v.y + v.z * v.z + v.w * v.w;
            uint2 h; cvt4h(v, h);
            uint32_t off = SM_A + a_rowpart + (a_sw ^ (uint32_t)((acol0 + 4 * i) * 2));
            *(uint2*)(smem + off) = h;
        }
        CP_WAIT0();
    }
    __syncthreads();

    // ---- per-lane ldmatrix address constants ----
    const int g = lane >> 3, j = lane & 7;
    uint32_t arow[2];
    #pragma unroll
    for (int mt = 0; mt < 2; mt++)
        arow[mt] = (uint32_t)((mw * 4 + mt * 2 + (g & 1)) * 1024 + j * 128);
    const uint32_t asw  = (uint32_t)(j * 16);
    const uint32_t akh  = (uint32_t)((g >> 1) * 16);
    uint32_t bfix[2];
    #pragma unroll
    for (int p = 0; p < 2; p++) {
        int nb = nw * 32 + (2 * p + (g >> 1)) * 8;
        bfix[p] = (uint32_t)((g & 1) * 1024 + j * 128 + ((j * 16) ^ (nb * 2)));
    }

    float acc[2][4][4];
    #pragma unroll
    for (int mt = 0; mt < 2; mt++)
        #pragma unroll
        for (int na4 = 0; na4 < 4; na4++)
            #pragma unroll
            for (int q = 0; q < 4; q++) acc[mt][na4][q] = 0.f;

    // ---- main loop over K chunks ----
    for (int kt = 0; kt < NCH; kt++) {
        if (kt < NCH - 1) {
            const float4* xg = (const float4*)(x + (rowBase + arow_t) * D + (kt + 1) * KT + acol0);
            #pragma unroll
            for (int i = 0; i < 8; i++) va[i] = xg[i];
            stage_b(kt + 1, (kt + 1) & 1);
            CP_COMMIT();
        }

        const uint32_t abase = sb + SM_A + (uint32_t)((kt & 1) * A_BUF);
        const uint32_t bbase = sb + SM_B + (uint32_t)((kt & 1) * B_BUF);
        #pragma unroll
        for (int kk = 0; kk < 4; kk++) {
            uint32_t ah[2][4], bq[4][2];
            uint32_t ac = asw ^ (akh + (uint32_t)(kk * 32));
            ldsm4(ah[0], abase + arow[0] + ac);
            ldsm4(ah[1], abase + arow[1] + ac);
            #pragma unroll
            for (int p = 0; p < 2; p++) {
                uint32_t t4[4];
                ldsm4t(t4, bbase + bfix[p] + (uint32_t)(kk * 2048));
                bq[2*p][0] = t4[0]; bq[2*p][1] = t4[1];
                bq[2*p+1][0] = t4[2]; bq[2*p+1][1] = t4[3];
            }
            #pragma unroll
            for (int mt = 0; mt < 2; mt++)
                #pragma unroll
                for (int na4 = 0; na4 < 4; na4++)
                    mma16816(acc[mt][na4], ah[mt], bq[na4]);
        }

        if (kt < NCH - 1) {   // stage A chunk kt+1 into the other buffer
            uint32_t base = SM_A + (uint32_t)(((kt + 1) & 1) * A_BUF);
            #pragma unroll
            for (int i = 0; i < 8; i++) {
                float4 v = va[i];
                na += v.x * v.x + v.y * v.y + v.z * v.z + v.w * v.w;
                uint2 h; cvt4h(v, h);
                uint32_t off = base + a_rowpart + (a_sw ^ (uint32_t)((acol0 + 4 * i) * 2));
                *(uint2*)(smem + off) = h;
            }
            CP_WAIT0();
        }
        __syncthreads();
    }

    // ---- row norms: pair-reduce (two threads per row, adjacent lanes) ----
    {
        float s = na + __shfl_xor_sync(0xffffffffu, na, 1);
        if ((tid & 1) == 0) xn2s[arow_t] = s;
    }
    __syncthreads();

    // ---- epilogue: scale + store ----
    const int gr = lane >> 2, ci = lane & 3;
    #pragma unroll
    for (int mt = 0; mt < 2; mt++) {
        #pragma unroll
        for (int rr = 0; rr < 2; rr++) {
            int row = mw * 32 + mt * 16 + rr * 8 + gr;
            float n2 = xn2s[row];
            float invxn = rsqrtf(n2);
            float xn = n2 * invxn;
            float* og = out + (rowBase + row) * NWAY;
            #pragma unroll
            for (int na4 = 0; na4 < 4; na4++) {
                int c0 = nw * 32 + na4 * 8 + ci * 2;
                float d0 = acc[mt][na4][rr * 2 + 0];
                float d1 = acc[mt][na4][rr * 2 + 1];
                float den0 = xn * spn[c0], den1 = xn * spn[c0 + 1];
                float s0 = (den0 < 1e-8f) ? 1e8f : invxn * sipn[c0];
                float s1 = (den1 < 1e-8f) ? 1e8f : invxn * sipn[c0 + 1];
                *(float2*)(og + c0) = make_float2(-d0 * s0, -d1 * s1);
            }
        }
    }
}

extern "C" void kernel_launch(void* const* d_in, const int* in_sizes, int n_in,
                              void* d_out, int out_size) {
    const float* x      = (const float*)d_in[0];
    const float* protos = (const float*)d_in[1];
    float* out          = (float*)d_out;
    int B = in_sizes[0] / D;   // 65536

    cudaFuncSetAttribute(cosine_hmma_kernel,
                         cudaFuncAttributeMaxDynamicSharedMemorySize, SMEM_TOTAL);

    proto_prep_kernel<<<NWAY, 128>>>(protos);
    cosine_hmma_kernel<<<B / MT, NTH, SMEM_TOTAL>>>(x, out);
}